// round 17
// baseline (speedup 1.0000x reference)
#include <cuda_runtime.h>
#include <cstdint>

// Problem constants
#define NB   64
#define NT   2048
#define EMBD 32
#define HID  256
#define KTOT 288
#define USLICE 8             // producers per group
#define BSLICE 16            // batch groups
#define NCTA  128
#define UPC   32             // units per CTA
#define NROWS 128            // 4 gates x 32 units
#define BPC   4              // batches per CTA
#define NTHREADS 256         // 4 k-segments x (32 rg x 2 bq)
#define NSEG 4
#define SEGK 64              // h k-values per segment (2 producers each)
#define XESEG 8              // xe k-values per segment

#define WJ   292             // j stride (floats)
#define WRG  1188            // rg stride; %32==4
#define ZPAD 264             // z (h-only) row stride; %32==8; 16B-aligned
#define XEP  36              // xe row stride
#define XEBUF (BPC * XEP)    // 144 floats per xe buffer
#define GSTR 9
#define GSEG (NROWS * GSTR)  // 1152

// SMEM float offsets
#define W_F   0
// W size = 31*WRG + 3*WJ + KTOT = 37992 -> 38000
#define Z_F   38000                    // [BPC][ZPAD]   h only (cols = unit 0..255)
#define XE_F  (Z_F + BPC * ZPAD)       // 39056  [2][BPC][XEP]
#define GP_F  (XE_F + 2 * XEBUF)       // 39344
#define BS_F  (GP_F + NSEG * GSEG)     // 43952
#define LEN_F (BS_F + NROWS)           // 44080
#define ML_F  (LEN_F + NB)             // 44144
#define SM_FLOATS (ML_F + 4)           // 44148 (~177 KB)

// Persistent cross-CTA state
__device__ float g_H[2][NB * HID];        // [buf][batch*HID + unit]
__device__ int   g_flag[BSLICE][USLICE];  // steps completed by producer (us,bsl)

__global__ void lstm_init_kernel() {
    int i = threadIdx.x;
    if (i < BSLICE * USLICE) ((int*)g_flag)[i] = 0;
}

__device__ __forceinline__ float sigf(float x)  { return 1.0f / (1.0f + __expf(-x)); }
__device__ __forceinline__ float tanha(float x) { return 2.0f / (1.0f + __expf(-2.0f * x)) - 1.0f; }

__device__ __forceinline__ int ld_acq(const int* p) {
    int v;
    asm volatile("ld.acquire.gpu.b32 %0, [%1];" : "=r"(v) : "l"(p));
    return v;
}

#define LDS2U64(a, b, addr) \
    asm volatile("ld.shared.v2.u64 {%0,%1}, [%2];" : "=l"(a), "=l"(b) : "r"(addr))
#define FMA2(acc, w, z) \
    asm volatile("fma.rn.f32x2 %0, %1, %2, %0;" : "+l"(acc) : "l"(w), "l"(z))
#define SEGBAR(id) \
    asm volatile("bar.sync %0, 64;" :: "r"(id) : "memory")

__global__ void __launch_bounds__(NTHREADS, 1)
lstm_persist_kernel(const int* __restrict__ x,        // [NB, NT]
                    const int* __restrict__ lengths,  // [NB]
                    const float* __restrict__ emb,    // [VOCAB, EMBD]
                    const float* __restrict__ W_ih,   // [4*HID, EMBD]
                    const float* __restrict__ W_hh,   // [4*HID, HID]
                    const float* __restrict__ b_ih,   // [4*HID]
                    const float* __restrict__ b_hh,   // [4*HID]
                    float* __restrict__ out)          // [NB, 1, HID]
{
    extern __shared__ float sm[];
    float* w_s  = sm + W_F;                  // [rg 0..31][j 0..3][k 0..287]
    float* z_s  = sm + Z_F;                  // [BPC][ZPAD]  h cols 0..255
    float* xe_s = sm + XE_F;                 // [2][BPC][XEP]
    float* gp   = sm + GP_F;                 // [NSEG][NROWS][GSTR]
    float* bs   = sm + BS_F;
    int* lenS   = (int*)(sm + LEN_F);
    int* mlS    = (int*)(sm + ML_F);

    const int tid = threadIdx.x;
    const int cta = blockIdx.x;
    const int us  = cta & (USLICE - 1);      // 0..7
    const int bsl = cta >> 3;                // 0..15
    const int u0  = us * UPC;
    const int bb0 = bsl * BPC;

    // ---- one-time staging: W rows (row r = g*32 + du), biases, lengths ----
    for (int idx = tid; idx < NROWS * KTOT; idx += NTHREADS) {
        int r = idx / KTOT;
        int k = idx - r * KTOT;
        int g = r >> 5, du = r & 31;
        int grow = g * HID + u0 + du;
        float v = (k < EMBD) ? W_ih[grow * EMBD + k]
                             : W_hh[grow * HID + (k - EMBD)];
        w_s[(r >> 2) * WRG + (r & 3) * WJ + k] = v;
    }
    if (tid < NROWS) {
        int g = tid >> 5, du = tid & 31;
        int grow = g * HID + u0 + du;
        bs[tid] = b_ih[grow] + b_hh[grow];
    }
    if (tid < NB) lenS[tid] = lengths[tid];
    __syncthreads();
    if (tid == 0) {
        int m = 1;
        for (int b = 0; b < NB; b++) m = max(m, lenS[b]);
        *mlS = m;
    }
    // zero h region of z (t=0 reads zeros)
    for (int i = tid; i < BPC * HID; i += NTHREADS) {
        int b = i >> 8, u = i & 255;
        z_s[b * ZPAD + u] = 0.0f;
    }
    // gather xe(0) into xe buf 0
    if (tid < 8 * BPC) {
        int b = tid >> 3, q = tid & 7;
        int tok = x[(bb0 + b) * NT + 0];
        float4 v = ((const float4*)(emb + (size_t)tok * EMBD))[q];
        *(float4*)(xe_s + b * XEP + q * 4) = v;
    }
    __syncthreads();
    const int maxlen = *mlS;

    // shared base for asm addressing
    uint32_t sb;
    asm("{ .reg .u64 t; cvta.to.shared.u64 t, %1; cvt.u32.u64 %0, t; }"
        : "=r"(sb) : "l"(sm));

    // GEMM mapping: tid = seg*64 + rg*2 + bq
    const int seg = tid >> 6;                // 0..3
    const int li  = tid & 63;                // lane within segment
    const int rg  = (tid >> 1) & 31;         // rows 4rg..4rg+3
    const int bq  = tid & 1;                 // batches bq, bq+2
    const uint32_t wbase = sb + (uint32_t)(W_F + rg * WRG) * 4u;
    const uint32_t wkx   = wbase + (uint32_t)(seg * XESEG) * 4u;          // xe slice
    const uint32_t wkm   = wbase + (uint32_t)(EMBD + seg * SEGK) * 4u;    // h slice
    const uint32_t zmA   = sb + (uint32_t)(Z_F + bq * ZPAD + seg * SEGK) * 4u;
    const uint32_t zmB   = zmA + (uint32_t)(2 * ZPAD) * 4u;
    const uint32_t xeA0  = sb + (uint32_t)(XE_F + bq * XEP + seg * XESEG) * 4u;
    const uint32_t xeB0  = xeA0 + (uint32_t)(2 * XEP) * 4u;
    float* gpb = gp + seg * GSEG;

    // h staging mapping: segment fragment = units [64s..64s+64) x 4 batches
    const int hb_b = li >> 4;                // 0..3
    const int hb_u = (li & 15) * 4;          // 0..60

    // xe gather mapping (li < 8): batch, quad-within-slice
    const int xg_b = li >> 1, xg_q = li & 1;

    // phase-2 mapping (tid < 128)
    const int u_l = tid >> 2;
    const int b2  = tid & 3;
    const int bg  = bb0 + (b2 & 3);
    const int uu  = u0 + (u_l & 31);
    const int mylen = (tid < 128) ? lenS[bg] : 0;
    float c_r = 0.0f, h_r = 0.0f;

    for (int t = 0; t < maxlen; t++) {
        // ---- per-segment hand-off: poll MY 2 producers, stage MY fragment ----
        if (t > 0) {
            if (li < 2) {
                const int* f = &g_flag[bsl][2 * seg + li];
                while (ld_acq(f) < t) { }
            }
            SEGBAR(seg + 1);
            float4 hv;
            {
                const float* src = g_H[t & 1] +
                    (size_t)(bb0 + hb_b) * HID + seg * SEGK + hb_u;
                asm volatile("ld.volatile.global.v4.f32 {%0,%1,%2,%3}, [%4];"
                             : "=f"(hv.x), "=f"(hv.y), "=f"(hv.z), "=f"(hv.w)
                             : "l"(src));
            }
            *(float4*)(z_s + hb_b * ZPAD + seg * SEGK + hb_u) = hv;
            SEGBAR(seg + 1);
        }

        // ---- partials: xe slice (k in [8s,8s+8)) + h slice (k in [64s,64s+64)) ----
        unsigned long long A[4][2];
        #pragma unroll
        for (int j = 0; j < 4; j++) { A[j][0] = 0ull; A[j][1] = 0ull; }
        {
            const uint32_t xoff = (t & 1) ? (uint32_t)(XEBUF * 4) : 0u;
            const uint32_t xA = xeA0 + xoff, xB = xeB0 + xoff;
            #pragma unroll
            for (int k = 0; k < XESEG; k += 4) {
                unsigned long long Z01a, Z23a, Z01b, Z23b;
                LDS2U64(Z01a, Z23a, xA + k * 4);
                LDS2U64(Z01b, Z23b, xB + k * 4);
                #pragma unroll
                for (int j = 0; j < 4; j++) {
                    unsigned long long W01, W23;
                    LDS2U64(W01, W23, wkx + (uint32_t)(j * WJ + k) * 4u);
                    FMA2(A[j][0], W01, Z01a); FMA2(A[j][0], W23, Z23a);
                    FMA2(A[j][1], W01, Z01b); FMA2(A[j][1], W23, Z23b);
                }
            }
        }
        #pragma unroll 4
        for (int k = 0; k < SEGK; k += 4) {
            unsigned long long Z01a, Z23a, Z01b, Z23b;
            LDS2U64(Z01a, Z23a, zmA + k * 4);
            LDS2U64(Z01b, Z23b, zmB + k * 4);
            #pragma unroll
            for (int j = 0; j < 4; j++) {
                unsigned long long W01, W23;
                LDS2U64(W01, W23, wkm + (uint32_t)(j * WJ + k) * 4u);
                FMA2(A[j][0], W01, Z01a); FMA2(A[j][0], W23, Z23a);
                FMA2(A[j][1], W01, Z01b); FMA2(A[j][1], W23, Z23b);
            }
        }
        // write partial gate sums (lo+hi of k-split accumulators)
        #pragma unroll
        for (int j = 0; j < 4; j++) {
            float ga = __uint_as_float((uint32_t)A[j][0]) +
                       __uint_as_float((uint32_t)(A[j][0] >> 32));
            float gb = __uint_as_float((uint32_t)A[j][1]) +
                       __uint_as_float((uint32_t)(A[j][1] >> 32));
            gpb[(4 * rg + j) * GSTR + bq]     = ga;
            gpb[(4 * rg + j) * GSTR + bq + 2] = gb;
        }
        __syncthreads();

        // ---- phase 2 (tid < 128): reduce 4 partials + bias, activations ----
        if (tid < 128) {
            float gate[4];
            #pragma unroll
            for (int g = 0; g < 4; g++) {
                int r = g * UPC + u_l;
                float s = bs[r];
                #pragma unroll
                for (int sg = 0; sg < NSEG; sg++)
                    s += gp[sg * GSEG + r * GSTR + b2];
                gate[g] = s;
            }
            float iv = sigf(gate[0]), fv = sigf(gate[1]);
            float gv = tanha(gate[2]), ov = sigf(gate[3]);
            float cn = fmaf(fv, c_r, iv * gv);
            float hn = ov * tanha(cn);
            if (t < mylen) { c_r = cn; h_r = hn; }
            g_H[(t + 1) & 1][bg * HID + uu] = h_r;
        }
        __syncthreads();   // all g_H stores issued CTA-wide

        // ---- publish: release-store orders prior global writes ----
        if (tid == 0) {
            asm volatile("st.release.gpu.b32 [%0], %1;"
                         :: "l"(&g_flag[bsl][us]), "r"(t + 1) : "memory");
        }

        // ---- per-segment xe(t+1) gather into xe buf (t+1)&1 ----
        // ordered for segment readers by next iteration's SEGBAR pair.
        if (t + 1 < maxlen && li < 8) {
            int tok = x[(bb0 + xg_b) * NT + (t + 1)];
            float4 v = ((const float4*)(emb + (size_t)tok * EMBD))[2 * seg + xg_q];
            *(float4*)(xe_s + ((t + 1) & 1) * XEBUF + xg_b * XEP
                       + seg * XESEG + xg_q * 4) = v;
        }
    }

    // final frozen h == reference out[:, -1, :]
    if (tid < 128) out[bg * HID + uu] = h_r;
}

extern "C" void kernel_launch(void* const* d_in, const int* in_sizes, int n_in,
                              void* d_out, int out_size) {
    const int*   x       = (const int*)d_in[0];
    const int*   lengths = (const int*)d_in[1];
    const float* emb     = (const float*)d_in[2];
    const float* W_ih    = (const float*)d_in[3];
    const float* W_hh    = (const float*)d_in[4];
    const float* b_ih    = (const float*)d_in[5];
    const float* b_hh    = (const float*)d_in[6];
    float* out = (float*)d_out;

    const int smem_bytes = SM_FLOATS * (int)sizeof(float) + 32;

    cudaFuncSetAttribute(lstm_persist_kernel,
                         cudaFuncAttributeMaxDynamicSharedMemorySize, smem_bytes);

    lstm_init_kernel<<<1, 128>>>();
    lstm_persist_kernel<<<NCTA, NTHREADS, smem_bytes>>>(
        x, lengths, emb, W_ih, W_hh, b_ih, b_hh, out);
}